// round 15
// baseline (speedup 1.0000x reference)
#include <cuda_runtime.h>
#include <cuda_bf16.h>
#include <math.h>

#define NN    4096
#define TT    8
#define RR    16
#define HH    8
#define BB    21
#define TPB   1024            // fill threads per block; 1 j-column per thread
#define NWIN  4               // j-windows per row (4096 / 1024)
#define CAPW  40              // max edges per (row,window); Poisson(8), P(>40) ~ 1e-16
#define CPAD  32              // counter stride: 128 B -> one counter per L2 line

// __device__ scratch (no allocation allowed in kernel_launch)
__device__ int          g_cnt[NN * NWIN * CPAD];   // counter w at g_cnt[w*CPAD]
__device__ unsigned int g_buck[NN * NWIN * CAPW];  // packed (rel<<12)|dst

// ---------------------------------------------------------------------------
__global__ void reset_kernel()
{
    int w = blockIdx.x * blockDim.x + threadIdx.x;
    if (w < NN * NWIN) g_cnt[w * CPAD] = 0;
}

// Bucket edges by (src row, dst window). Order nondeterministic; fill sums all
// entries, so result is order-insensitive (last-ulp fp rounding only).
__global__ void __launch_bounds__(256)
bucket_kernel(const int* __restrict__ edge_src,
              const int* __restrict__ edge_dst,
              const int* __restrict__ edge_rel,
              int n_edges)
{
    int e = blockIdx.x * blockDim.x + threadIdx.x;
    if (e >= n_edges) return;
    const int s = edge_src[e];
    const int d = edge_dst[e];
    const int r = edge_rel[e];
    const int w = s * NWIN + (d >> 10);           // window = dst / 1024
    int pos = atomicAdd(&g_cnt[w * CPAD], 1);
    if (pos < CAPW)
        g_buck[w * CAPW + pos] = ((unsigned)r << 12) | (unsigned)d;
}

// ---------------------------------------------------------------------------
// Fused fill: out[h,i,j] = typepair[tt[i],tt[j],h] (+ temporal for seed rows)
//                          (+ adj_rel_bias[rel,h] for edges (i -> j))
// One thread per (i,j); 8-register accumulator; exact-match edge scan over the
// block's precomputed window bucket; 8 coalesced streaming scalar stores.
// ---------------------------------------------------------------------------
__global__ void __launch_bounds__(TPB)
fill_kernel(const int*   __restrict__ token_type,
            const float* __restrict__ time_vec,
            const float* __restrict__ typepair_bias,  // [T,T,H] = 512
            const float* __restrict__ temp_bias,      // [B,H]   = 168
            const float* __restrict__ adj_rel_bias,   // [R,H]   = 128
            const int*   __restrict__ seed_ptr,       // may be null
            float*       __restrict__ out)
{
    __shared__ float        s_tp[TT * TT * HH];  // 512
    __shared__ float        s_tb[BB * HH];       // 168
    __shared__ float        s_adj[RR * HH];      // 128
    __shared__ unsigned int s_edges[CAPW];

    const int tid = threadIdx.x;
    const int i   = blockIdx.y;
    const int w   = i * NWIN + blockIdx.x;       // this block's (row,window) id

    // Parallel prologue: tables, count, and edge entries all load concurrently
    // (entries speculative; masked by count after the sync).
    if (tid < TT * TT * HH)                       s_tp[tid]       = typepair_bias[tid];
    else if (tid < TT * TT * HH + BB * HH)        s_tb[tid - 512] = temp_bias[tid - 512];
    else if (tid < TT * TT * HH + BB * HH + RR * HH)
                                                  s_adj[tid - 680] = adj_rel_bias[tid - 680];
    const int c = g_cnt[w * CPAD];                // uniform load, all threads
    if (tid < CAPW) s_edges[tid] = g_buck[w * CAPW + tid];   // speculative
    const int tti = token_type[i];                // uniform
    __syncthreads();

    const int ecnt = (c < CAPW) ? c : CAPW;

    const int j   = blockIdx.x * TPB + tid;
    const int ttj = token_type[j];                // coalesced 4B loads

    const int seed = seed_ptr ? *seed_ptr : 128;

    // 8-register accumulator
    float acc[HH];
    const float* tp = s_tp + (tti * TT + ttj) * HH;
#pragma unroll
    for (int h = 0; h < HH; h++) acc[h] = tp[h];

    if (i < seed) {
        const float dt = time_vec[j] - time_vec[i];
        float sg  = (dt > 0.f) ? 1.f : ((dt < 0.f) ? -1.f : 0.f);
        float sl  = sg * log1pf(fabsf(dt) + 1e-6f);
        float nrm = (fminf(fmaxf(sl, -5.f), 5.f) + 5.f) * (1.0f / 10.0f);
        int bk = (int)floorf(nrm * (float)(BB - 1));
        bk = min(max(bk, 0), BB - 1);
        const float* tb = s_tb + bk * HH;
#pragma unroll
        for (int h = 0; h < HH; h++) acc[h] += tb[h];
    }

    // Exact-match edge scan (~8 entries, smem broadcast)
    for (int e = 0; e < ecnt; e++) {
        const unsigned p = s_edges[e];
        if ((p & 0xFFFu) == (unsigned)j) {
            const float* ab = s_adj + (p >> 12) * HH;
#pragma unroll
            for (int h = 0; h < HH; h++) acc[h] += ab[h];
        }
    }

    const size_t base = (size_t)i * NN + (size_t)j;
#pragma unroll
    for (int h = 0; h < HH; h++)
        __stcs(out + (size_t)h * NN * NN + base, acc[h]);  // 128B/warp/plane, streaming
}

// ---------------------------------------------------------------------------
extern "C" void kernel_launch(void* const* d_in, const int* in_sizes, int n_in,
                              void* d_out, int out_size)
{
    const int*   token_type = (const int*)  d_in[0];
    const int*   edge_src   = (const int*)  d_in[1];
    const int*   edge_dst   = (const int*)  d_in[2];
    const int*   edge_rel   = (const int*)  d_in[3];
    const float* time_vec   = (const float*)d_in[4];

    // seed_count may appear as a 1-element int tensor at slot 5, or be absent.
    const int*   seed_ptr = nullptr;
    int bias_base = 5;
    if (n_in >= 9 && in_sizes[5] == 1) {
        seed_ptr  = (const int*)d_in[5];
        bias_base = 6;
    }
    const float* adj_rel_bias  = (const float*)d_in[bias_base + 0];  // [R,H]
    const float* typepair_bias = (const float*)d_in[bias_base + 1];  // [T,T,H]
    const float* temp_bias     = (const float*)d_in[bias_base + 2];  // [B,H]

    float* out = (float*)d_out;
    const int n_edges = in_sizes[1];

    reset_kernel<<<(NN * NWIN + 255) / 256, 256>>>();
    bucket_kernel<<<(n_edges + 255) / 256, 256>>>(edge_src, edge_dst, edge_rel, n_edges);

    // Fused fill: grid (4 windows, 4096 rows), 1024 threads, 1 j per thread
    dim3 fgrid(NWIN, NN);
    fill_kernel<<<fgrid, TPB>>>(token_type, time_vec, typepair_bias, temp_bias,
                                adj_rel_bias, seed_ptr, out);
}